// round 14
// baseline (speedup 1.0000x reference)
#include <cuda_runtime.h>
#include <cuda_bf16.h>
#include <cstdint>

#define NS 4
#define TS 136                     // T slot stride in floats (128 batches + 8 pad)
// smem (bytes): T = float[257][136], 2 chunk bufs, base-prob scratch
#define SB_BUF  139808             // 257*136*4
#define SB_PB   176672             // SB_BUF + 2*18432
#define SMEM_BYTES 178720          // 1 CTA/SM
#define PLOG_SMEM ((64*65 + 16*64) * 4)   // 20736

__device__ __align__(256) __nv_bfloat16 g_kdh[256*256*72];
__device__ __align__(256) __nv_bfloat16 g_kdl[256*256*72];
__device__ __align__(256) __nv_bfloat16 g_vh [256*256*72];
__device__ __align__(256) __nv_bfloat16 g_vl [256*256*72];
__device__ __align__(256) __nv_bfloat16 g_qh [2048*72];
__device__ __align__(256) __nv_bfloat16 g_ql [2048*72];
__device__ float g_plog[255*2048];  // fp32 logits, top-255 nodes

__device__ __forceinline__ uint32_t cvta(const void* p){
    uint32_t a; asm("{.reg .u64 t; cvta.to.shared.u64 t,%1; cvt.u32.u64 %0,t;}":"=r"(a):"l"(p)); return a;
}
__device__ __forceinline__ void ldsm4(uint32_t r[4], uint32_t a){
    asm volatile("ldmatrix.sync.aligned.m8n8.x4.shared.b16 {%0,%1,%2,%3},[%4];"
        :"=r"(r[0]),"=r"(r[1]),"=r"(r[2]),"=r"(r[3]):"r"(a));
}
__device__ __forceinline__ void ldsm4t(uint32_t r[4], uint32_t a){
    asm volatile("ldmatrix.sync.aligned.m8n8.x4.trans.shared.b16 {%0,%1,%2,%3},[%4];"
        :"=r"(r[0]),"=r"(r[1]),"=r"(r[2]),"=r"(r[3]):"r"(a));
}
__device__ __forceinline__ void mma(float c[4], const uint32_t a[4], const uint32_t b0, const uint32_t b1){
    asm volatile("mma.sync.aligned.m16n8k16.row.col.f32.bf16.bf16.f32 "
        "{%0,%1,%2,%3},{%4,%5,%6,%7},{%8,%9},{%0,%1,%2,%3};"
        :"+f"(c[0]),"+f"(c[1]),"+f"(c[2]),"+f"(c[3])
        :"r"(a[0]),"r"(a[1]),"r"(a[2]),"r"(a[3]),"r"(b0),"r"(b1));
}
__device__ __forceinline__ void cp16(uint32_t d, const void* s){
    asm volatile("cp.async.cg.shared.global [%0],[%1],16;"::"r"(d),"l"(s));
}
#define CP_COMMIT() asm volatile("cp.async.commit_group;":::"memory")
#define CP_WAIT(N)  asm volatile("cp.async.wait_group %0;"::"n"(N):"memory")
__device__ __forceinline__ void split2(float x, __nv_bfloat16& h, __nv_bfloat16& lo){
    h = __float2bfloat16(x); lo = __float2bfloat16(x - __bfloat162float(h));
}
__device__ __forceinline__ void splitpair(float a, float b, uint32_t& hw, uint32_t& lw){
    __nv_bfloat16 ha, la, hb, lb;
    split2(a, ha, la); split2(b, hb, lb);
    hw = (uint32_t)__bfloat16_as_ushort(ha) | ((uint32_t)__bfloat16_as_ushort(hb) << 16);
    lw = (uint32_t)__bfloat16_as_ushort(la) | ((uint32_t)__bfloat16_as_ushort(lb) << 16);
}
__device__ __forceinline__ float fast_sigmoid(float x){
    float e; asm("ex2.approx.f32 %0,%1;":"=f"(e):"f"(-x*1.4426950408889634f));
    float r; asm("rcp.approx.f32 %0,%1;":"=f"(r):"f"(1.f+e));
    return r;
}
// hi-plane slot of leaf-pair P (bank-decorrelated, in-place-safe permutation)
__device__ __forceinline__ int slotH(int P){
    return (P < 64) ? (2*P + ((P >> 1) & 1))
                    : (2*(P - 64) + 1 - (((P - 64) >> 1) & 1));
}

// ------------------- fused prep: KD | V | Q | PLOG -------------------
__global__ __launch_bounds__(256)
void prep_all(const float* __restrict__ q, const float* __restrict__ tk,
              const float* __restrict__ tv)
{
    const int bid = blockIdx.x, tid = threadIdx.x;
    const int lr = tid >> 6, k = tid & 63;

    if (bid < 16384){                       // ---- KD ----
        int gr = bid*4 + lr;
        int s = gr >> 8, r = gr & 255;
        float d = 0.f;
        if (r < 255){
            int rp = r+1, e = 31-__clz(rp), pj = rp-(1<<e);
            int j = e ? (int)(__brev((unsigned)pj) >> (32-e)) : 0;
            size_t node = (((size_t)1<<(e+8))-1) + (size_t)s*(1<<e) + j;
            d = tk[node*128 + k] - tk[node*128 + 64 + k];
        }
        __nv_bfloat16 h, lo; split2(d, h, lo);
        g_kdh[(size_t)gr*72 + k] = h; g_kdl[(size_t)gr*72 + k] = lo;
    } else if (bid < 32768){                // ---- V ----
        int gr = (bid - 16384)*4 + lr;
        int s = gr >> 8, r = gr & 255;
        size_t leaf = (size_t)s*256 + (__brev((unsigned)r) >> 24);
        float v = tv[leaf*64 + k];
        __nv_bfloat16 h, lo; split2(v, h, lo);
        g_vh[(size_t)gr*72 + k] = h; g_vl[(size_t)gr*72 + k] = lo;
    } else if (bid < 33280){                // ---- Q ----
        int b = (bid - 32768)*4 + lr;
        __nv_bfloat16 h, lo; split2(q[(size_t)b*64 + k], h, lo);
        g_qh[(size_t)b*72 + k] = h; g_ql[(size_t)b*72 + k] = lo;
    } else {                                // ---- PLOG ----
        extern __shared__ float ps[];
        float* qs = ps;                     // [k][b] stride 65
        float* ks = ps + 64*65;             // [j][k] 16 nodes
        int pb = bid - 33280;
        int btile = pb >> 4, slice = pb & 15;
        int b_base = btile * 64, n0 = slice * 16;
        for (int i = tid; i < 64*64; i += 256){
            int b = i >> 6, kk = i & 63;
            qs[kk*65 + b] = q[(size_t)(b_base + b)*64 + kk];
        }
        for (int i = tid; i < 16*64; i += 256){
            int j = i >> 6, kk = i & 63;
            int n = n0 + j;
            ks[i] = (n < 255) ? (tk[(size_t)n*128 + kk] - tk[(size_t)n*128 + 64 + kk]) : 0.f;
        }
        __syncthreads();
        int b = tid & 63, sub = tid >> 6;
        #pragma unroll
        for (int j2 = 0; j2 < 4; j2++){
            int j = sub*4 + j2, n = n0 + j;
            if (n >= 255) break;
            float acc = 0.f;
            #pragma unroll 16
            for (int kk = 0; kk < 64; kk++)
                acc = fmaf(qs[kk*65 + b], ks[j*64 + kk], acc);
            g_plog[(size_t)n*2048 + b_base + b] = acc;
        }
    }
}

// ----------------------------- main kernel -----------------------------
// BT=128 per CTA. T: slot-major float[257][136]. slot 0 = base prob;
// slot 2^e+pos = sigma(level e); cum(pos) at slot pos. Level 7 packs
// split-bf16 leaf pairs in place via slotH. Warp tiles 32x32 in both GEMMs.
__global__ __launch_bounds__(256, 1)
void tree_kernel(float* __restrict__ out)
{
    extern __shared__ char smc[];
    float* fT = (float*)smc;
    uint32_t* uT = (uint32_t*)smc;
    float* fPB = (float*)(smc + SB_PB);
    const uint32_t SB = cvta(smc);
    const int tid = threadIdx.x, w = tid >> 5, l = tid & 31;
    const int btile = blockIdx.x, sg = blockIdx.y;
    const int b_base = btile * 128;
    const int rg = w >> 1, cg = w & 1;       // 4 row-groups x 2 col-groups
    const int total = NS * 8;

    auto issue = [&](int t){
        if (t >= total) return;
        int c = t & 7, si = t >> 3;
        size_t off = ((size_t)(sg*NS + si)*256 + (size_t)(c & 3)*64)*72;
        const __nv_bfloat16 *ph = (c < 4) ? g_kdh + off : g_vh + off;
        const __nv_bfloat16 *pl = (c < 4) ? g_kdl + off : g_vl + off;
        uint32_t dst = SB + SB_BUF + (uint32_t)(t & 1)*18432;
        for (int i = tid; i < 576; i += 256){
            cp16(dst + i*16,        (const char*)ph + i*16);
            cp16(dst + 9216 + i*16, (const char*)pl + i*16);
        }
        CP_COMMIT();
    };

    issue(0); issue(1);

    // ---- Q fragments -> registers (2 row tiles of 16) ----
    uint32_t QAh[2][4][4], QAl[2][4][4];
    #pragma unroll
    for (int rt = 0; rt < 2; rt++){
        int r0 = b_base + rg*32 + rt*16 + (l >> 2);
        int c0 = 2 * (l & 3);
        #pragma unroll
        for (int kt = 0; kt < 4; kt++){
            int k0 = kt*16 + c0;
            QAh[rt][kt][0] = *(const uint32_t*)&g_qh[(size_t)r0*72 + k0];
            QAh[rt][kt][1] = *(const uint32_t*)&g_qh[(size_t)(r0+8)*72 + k0];
            QAh[rt][kt][2] = *(const uint32_t*)&g_qh[(size_t)r0*72 + k0 + 8];
            QAh[rt][kt][3] = *(const uint32_t*)&g_qh[(size_t)(r0+8)*72 + k0 + 8];
            QAl[rt][kt][0] = *(const uint32_t*)&g_ql[(size_t)r0*72 + k0];
            QAl[rt][kt][1] = *(const uint32_t*)&g_ql[(size_t)(r0+8)*72 + k0];
            QAl[rt][kt][2] = *(const uint32_t*)&g_ql[(size_t)r0*72 + k0 + 8];
            QAl[rt][kt][3] = *(const uint32_t*)&g_ql[(size_t)(r0+8)*72 + k0 + 8];
        }
    }

    // ---- 9 path logits per batch (coalesced; staged in T, dead before GEMM1) ----
    for (int i = tid; i < 9*128; i += 256){
        int n = i >> 7, b = i & 127;
        int node = (n < 7) ? ((1 << n) - 1 + (sg >> (6 - n)))
                           : (127 + 2*sg + (n - 7));
        fT[n*TS + b] = g_plog[(size_t)node*2048 + b_base + b];
    }
    __syncthreads();
    if (tid < 128){
        int b = tid;
        float common = 1.f;
        #pragma unroll
        for (int e = 0; e < 6; e++){
            int bit = (sg >> (5 - e)) & 1;
            float x = fT[e*TS + b];
            common *= fast_sigmoid(bit ? -x : x);
        }
        float s6  = fast_sigmoid(fT[6*TS + b]);
        float s7a = fast_sigmoid(fT[7*TS + b]);
        float s7b = fast_sigmoid(fT[8*TS + b]);
        fPB[0*128 + b] = common * s6 * s7a;
        fPB[1*128 + b] = common * s6 * (1.f - s7a);
        fPB[2*128 + b] = common * (1.f - s6) * s7b;
        fPB[3*128 + b] = common * (1.f - s6) * (1.f - s7b);
    }

    float acc2[2][4][4];
    #pragma unroll
    for (int rt = 0; rt < 2; rt++)
        #pragma unroll
        for (int i = 0; i < 4; i++)
            #pragma unroll
            for (int j = 0; j < 4; j++) acc2[rt][i][j] = 0.f;

    for (int si = 0; si < NS; si++){
        // ---------------- GEMM1: 4 passes of 64 n-columns ----------------
        for (int p = 0; p < 4; p++){
            int t = si*8 + p;
            if (t + 1 < total) CP_WAIT(1); else CP_WAIT(0);
            __syncthreads();
            uint32_t kb = SB + SB_BUF + (uint32_t)(t & 1)*18432;
            float a1[2][4][4];
            #pragma unroll
            for (int rt = 0; rt < 2; rt++)
                #pragma unroll
                for (int i = 0; i < 4; i++)
                    #pragma unroll
                    for (int j = 0; j < 4; j++) a1[rt][i][j] = 0.f;
            #pragma unroll
            for (int kt = 0; kt < 4; kt++){
                #pragma unroll
                for (int ntp = 0; ntp < 2; ntp++){
                    uint32_t bo = kb + (uint32_t)((
                        (cg*32 + ntp*16 + (((l >> 4) & 1) << 3) + (l & 7))*72
                        + kt*16 + (((l >> 3) & 1) << 3)) << 1);
                    uint32_t Bh[4], Bl[4];
                    ldsm4(Bh, bo); ldsm4(Bl, bo + 9216);
                    #pragma unroll
                    for (int rt = 0; rt < 2; rt++){
                        mma(a1[rt][2*ntp],   QAh[rt][kt], Bh[0], Bh[1]);
                        mma(a1[rt][2*ntp],   QAh[rt][kt], Bl[0], Bl[1]);
                        mma(a1[rt][2*ntp],   QAl[rt][kt], Bh[0], Bh[1]);
                        mma(a1[rt][2*ntp+1], QAh[rt][kt], Bh[2], Bh[3]);
                        mma(a1[rt][2*ntp+1], QAh[rt][kt], Bl[2], Bl[3]);
                        mma(a1[rt][2*ntp+1], QAl[rt][kt], Bh[2], Bh[3]);
                    }
                }
            }
            // sigma fused: store into slot-major T [1+node][b]
            #pragma unroll
            for (int rt = 0; rt < 2; rt++)
                #pragma unroll
                for (int nt = 0; nt < 4; nt++){
                    int r = rg*32 + rt*16 + (l >> 2);
                    int cc = p*64 + cg*32 + nt*8 + 2*(l & 3);
                    fT[(1 + cc)*TS + r]     = fast_sigmoid(a1[rt][nt][0]);
                    fT[(2 + cc)*TS + r]     = fast_sigmoid(a1[rt][nt][1]);
                    fT[(1 + cc)*TS + r + 8] = fast_sigmoid(a1[rt][nt][2]);
                    fT[(2 + cc)*TS + r + 8] = fast_sigmoid(a1[rt][nt][3]);
                }
            __syncthreads();
            if (t + 2 < total) issue(t + 2);
        }
        if (tid < 128) fT[tid] = fPB[si*128 + tid];   // slot 0
        __syncthreads();

        // ------- expansion: fused triple levels, warp-private 16 batches -------
        {
            const int wb = w * 16;
            // step A: levels 0,1,2 (1 parent -> 8); 8 float2 pairs per warp
            if (l < 8){
                int b2 = wb + 2*l;
                float2 v   = *(float2*)&fT[0*TS + b2];
                float2 s0  = *(float2*)&fT[1*TS + b2];
                float2 s10 = *(float2*)&fT[2*TS + b2];
                float2 s11 = *(float2*)&fT[3*TS + b2];
                float2 s2[4];
                #pragma unroll
                for (int j = 0; j < 4; j++) s2[j] = *(float2*)&fT[(4+j)*TS + b2];
                float2 a0{v.x*s0.x, v.y*s0.y}, a1v{v.x-a0.x, v.y-a0.y};
                float2 bb[4];
                bb[0] = {a0.x*s10.x,  a0.y*s10.y};  bb[2] = {a0.x-bb[0].x,  a0.y-bb[0].y};
                bb[1] = {a1v.x*s11.x, a1v.y*s11.y}; bb[3] = {a1v.x-bb[1].x, a1v.y-bb[1].y};
                #pragma unroll
                for (int j = 0; j < 4; j++){
                    float2 c0{bb[j].x*s2[j].x, bb[j].y*s2[j].y};
                    float2 c1{bb[j].x-c0.x,    bb[j].y-c0.y};
                    *(float2*)&fT[j*TS + b2]     = c0;
                    *(float2*)&fT[(j+4)*TS + b2] = c1;
                }
            }
            __syncwarp();
            // step B: levels 3,4,5 (8 parents -> 64); 64 items, 2 iters
            #pragma unroll
            for (int ii = 0; ii < 2; ii++){
                int it = l + ii*32;
                int pos = it >> 3, b2 = wb + 2*(it & 7);
                float2 v   = *(float2*)&fT[pos*TS + b2];
                float2 s3  = *(float2*)&fT[(8+pos)*TS + b2];
                float2 s40 = *(float2*)&fT[(16+pos)*TS + b2];
                float2 s41 = *(float2*)&fT[(24+pos)*TS + b2];
                float2 s5[4];
                #pragma unroll
                for (int j = 0; j < 4; j++) s5[j] = *(float2*)&fT[(32+8*j+pos)*TS + b2];
                float2 a0{v.x*s3.x, v.y*s3.y}, a1v{v.x-a0.x, v.y-a0.y};
                float2 bb[4];
                bb[0] = {a0.x*s40.x,  a0.y*s40.y};  bb[2] = {a0.x-bb[0].x,  a0.y-bb[0].y};
                bb[1] = {a1v.x*s41.x, a1v.y*s41.y}; bb[3] = {a1v.x-bb[1].x, a1v.y-bb[1].y};
                #pragma unroll
                for (int j = 0; j < 4; j++){
                    float2 c0{bb[j].x*s5[j].x, bb[j].y*s5[j].y};
                    float2 c1{bb[j].x-c0.x,    bb[j].y-c0.y};
                    *(float2*)&fT[(8*j+pos)*TS + b2]    = c0;
                    *(float2*)&fT[(32+8*j+pos)*TS + b2] = c1;
                }
            }
            __syncwarp();
            // level 6 (64 parents -> 128); 512 items
            for (int it = l; it < 512; it += 32){
                int pos = it >> 3, b2 = wb + 2*(it & 7);
                float2 v = *(float2*)&fT[pos*TS + b2];
                float2 s = *(float2*)&fT[(64+pos)*TS + b2];
                float2 c0{v.x*s.x, v.y*s.y};
                float2 c1{v.x-c0.x, v.y-c0.y};
                *(float2*)&fT[pos*TS + b2]      = c0;
                *(float2*)&fT[(64+pos)*TS + b2] = c1;
            }
            __syncwarp();
            // level 7 + split-pack (permuted slots); 512 items
            for (int it = l; it < 512; it += 32){
                int pp = it >> 3, b2 = wb + 2*(it & 7);
                float2 v0 = *(float2*)&fT[(2*pp)*TS + b2];
                float2 v1 = *(float2*)&fT[(2*pp+1)*TS + b2];
                float2 s0 = *(float2*)&fT[(128+2*pp)*TS + b2];
                float2 s1 = *(float2*)&fT[(129+2*pp)*TS + b2];
                float c0ax = v0.x*s0.x, c1ax = v0.x-c0ax;
                float c0bx = v1.x*s1.x, c1bx = v1.x-c0bx;
                float c0ay = v0.y*s0.y, c1ay = v0.y-c0ay;
                float c0by = v1.y*s1.y, c1by = v1.y-c0by;
                uint32_t h1x,l1x,h2x,l2x,h1y,l1y,h2y,l2y;
                splitpair(c0ax, c0bx, h1x, l1x);
                splitpair(c1ax, c1bx, h2x, l2x);
                splitpair(c0ay, c0by, h1y, l1y);
                splitpair(c1ay, c1by, h2y, l2y);
                int tt = (pp >> 1) & 1;
                int s1h = 2*pp + tt, s2h = 2*pp + 1 - tt;
                *(uint2*)&uT[s1h*TS + b2]       = make_uint2(h1x, h1y);
                *(uint2*)&uT[s2h*TS + b2]       = make_uint2(h2x, h2y);
                *(uint2*)&uT[(s1h+128)*TS + b2] = make_uint2(l1x, l1y);
                *(uint2*)&uT[(s2h+128)*TS + b2] = make_uint2(l2x, l2y);
            }
        }
        __syncthreads();

        // ---------------- GEMM2: 4 k-chunks, register accumulator ----------------
        for (int c = 0; c < 4; c++){
            int t = si*8 + 4 + c;
            if (t + 1 < total) CP_WAIT(1); else CP_WAIT(0);
            __syncthreads();
            uint32_t vb = SB + SB_BUF + (uint32_t)(t & 1)*18432;
            #pragma unroll
            for (int kt = 0; kt < 4; kt++){
                int Pb = c*32 + kt*8;
                int Pa = Pb + (l & 3), Pc = Pb + 4 + (l & 3);
                int sa = slotH(Pa), sc = slotH(Pc);
                uint32_t Ah[2][4], Al[2][4];
                #pragma unroll
                for (int rt = 0; rt < 2; rt++){
                    int r0 = rg*32 + rt*16 + (l >> 2);
                    Ah[rt][0] = uT[sa*TS + r0];
                    Ah[rt][1] = uT[sa*TS + r0 + 8];
                    Ah[rt][2] = uT[sc*TS + r0];
                    Ah[rt][3] = uT[sc*TS + r0 + 8];
                    Al[rt][0] = uT[(sa+128)*TS + r0];
                    Al[rt][1] = uT[(sa+128)*TS + r0 + 8];
                    Al[rt][2] = uT[(sc+128)*TS + r0];
                    Al[rt][3] = uT[(sc+128)*TS + r0 + 8];
                }
                #pragma unroll
                for (int dtp = 0; dtp < 2; dtp++){
                    uint32_t bo = vb + (uint32_t)((
                        (kt*16 + (((l >> 3) & 1) << 3) + (l & 7))*72
                        + cg*32 + dtp*16 + (((l >> 4) & 1) << 3)) << 1);
                    uint32_t Bh[4], Bl[4];
                    ldsm4t(Bh, bo); ldsm4t(Bl, bo + 9216);
                    #pragma unroll
                    for (int rt = 0; rt < 2; rt++){
                        mma(acc2[rt][2*dtp],   Ah[rt], Bh[0], Bh[1]);
                        mma(acc2[rt][2*dtp],   Ah[rt], Bl[0], Bl[1]);
                        mma(acc2[rt][2*dtp],   Al[rt], Bh[0], Bh[1]);
                        mma(acc2[rt][2*dtp+1], Ah[rt], Bh[2], Bh[3]);
                        mma(acc2[rt][2*dtp+1], Ah[rt], Bl[2], Bl[3]);
                        mma(acc2[rt][2*dtp+1], Al[rt], Bh[2], Bh[3]);
                    }
                }
            }
            __syncthreads();
            if (t + 2 < total) issue(t + 2);
        }
    }

    // ---------------- epilogue: one atomic pass per CTA ----------------
    #pragma unroll
    for (int rt = 0; rt < 2; rt++)
        #pragma unroll
        for (int dt = 0; dt < 4; dt++){
            int r = b_base + rg*32 + rt*16 + (l >> 2);
            int cc = cg*32 + dt*8 + 2*(l & 3);
            atomicAdd(&out[(size_t)r*64 + cc],         acc2[rt][dt][0]);
            atomicAdd(&out[(size_t)r*64 + cc + 1],     acc2[rt][dt][1]);
            atomicAdd(&out[(size_t)(r+8)*64 + cc],     acc2[rt][dt][2]);
            atomicAdd(&out[(size_t)(r+8)*64 + cc + 1], acc2[rt][dt][3]);
        }
}

extern "C" void kernel_launch(void* const* d_in, const int* in_sizes, int n_in,
                              void* d_out, int out_size) {
    const float* q  = (const float*)d_in[0];
    const float* tk = (const float*)d_in[1];
    const float* tv = (const float*)d_in[2];
    float* out = (float*)d_out;

    cudaFuncSetAttribute(tree_kernel,
                         cudaFuncAttributeMaxDynamicSharedMemorySize, SMEM_BYTES);

    cudaMemsetAsync(out, 0, (size_t)2048 * 64 * sizeof(float));
    prep_all<<<33792, 256, PLOG_SMEM>>>(q, tk, tv);
    tree_kernel<<<dim3(16, 64), 256, SMEM_BYTES>>>(out);
}

// round 15
// speedup vs baseline: 1.0113x; 1.0113x over previous
#include <cuda_runtime.h>
#include <cuda_bf16.h>
#include <cstdint>

#define NS 4
#define TS 136                     // T slot stride in floats (128 batches + 8 pad)
#define SB_BUF  139808             // T = 257*136*4
#define SB_PB   176672             // SB_BUF + 2*18432
#define SMEM_BYTES 178720          // 1 CTA/SM, 512 threads
#define PLOG_SMEM ((64*65 + 16*64) * 4)   // 20736

__device__ __align__(256) __nv_bfloat16 g_kdh[256*256*72];
__device__ __align__(256) __nv_bfloat16 g_kdl[256*256*72];
__device__ __align__(256) __nv_bfloat16 g_vh [256*256*72];
__device__ __align__(256) __nv_bfloat16 g_vl [256*256*72];
__device__ __align__(256) __nv_bfloat16 g_qh [2048*72];
__device__ __align__(256) __nv_bfloat16 g_ql [2048*72];
__device__ float g_plog[255*2048];

__device__ __forceinline__ uint32_t cvta(const void* p){
    uint32_t a; asm("{.reg .u64 t; cvta.to.shared.u64 t,%1; cvt.u32.u64 %0,t;}":"=r"(a):"l"(p)); return a;
}
__device__ __forceinline__ void ldsm4(uint32_t r[4], uint32_t a){
    asm volatile("ldmatrix.sync.aligned.m8n8.x4.shared.b16 {%0,%1,%2,%3},[%4];"
        :"=r"(r[0]),"=r"(r[1]),"=r"(r[2]),"=r"(r[3]):"r"(a));
}
__device__ __forceinline__ void ldsm4t(uint32_t r[4], uint32_t a){
    asm volatile("ldmatrix.sync.aligned.m8n8.x4.trans.shared.b16 {%0,%1,%2,%3},[%4];"
        :"=r"(r[0]),"=r"(r[1]),"=r"(r[2]),"=r"(r[3]):"r"(a));
}
__device__ __forceinline__ void mma(float c[4], const uint32_t a[4], const uint32_t b0, const uint32_t b1){
    asm volatile("mma.sync.aligned.m16n8k16.row.col.f32.bf16.bf16.f32 "
        "{%0,%1,%2,%3},{%4,%5,%6,%7},{%8,%9},{%0,%1,%2,%3};"
        :"+f"(c[0]),"+f"(c[1]),"+f"(c[2]),"+f"(c[3])
        :"r"(a[0]),"r"(a[1]),"r"(a[2]),"r"(a[3]),"r"(b0),"r"(b1));
}
__device__ __forceinline__ void cp16(uint32_t d, const void* s){
    asm volatile("cp.async.cg.shared.global [%0],[%1],16;"::"r"(d),"l"(s));
}
#define CP_COMMIT() asm volatile("cp.async.commit_group;":::"memory")
#define CP_WAIT(N)  asm volatile("cp.async.wait_group %0;"::"n"(N):"memory")
__device__ __forceinline__ void split2(float x, __nv_bfloat16& h, __nv_bfloat16& lo){
    h = __float2bfloat16(x); lo = __float2bfloat16(x - __bfloat162float(h));
}
__device__ __forceinline__ void splitpair(float a, float b, uint32_t& hw, uint32_t& lw){
    __nv_bfloat16 ha, la, hb, lb;
    split2(a, ha, la); split2(b, hb, lb);
    hw = (uint32_t)__bfloat16_as_ushort(ha) | ((uint32_t)__bfloat16_as_ushort(hb) << 16);
    lw = (uint32_t)__bfloat16_as_ushort(la) | ((uint32_t)__bfloat16_as_ushort(lb) << 16);
}
__device__ __forceinline__ float fast_sigmoid(float x){
    float e; asm("ex2.approx.f32 %0,%1;":"=f"(e):"f"(-x*1.4426950408889634f));
    float r; asm("rcp.approx.f32 %0,%1;":"=f"(r):"f"(1.f+e));
    return r;
}
__device__ __forceinline__ int slotH(int P){
    return (P < 64) ? (2*P + ((P >> 1) & 1))
                    : (2*(P - 64) + 1 - (((P - 64) >> 1) & 1));
}

// ------------------- fused prep: KD | V | Q | PLOG -------------------
__global__ __launch_bounds__(256)
void prep_all(const float* __restrict__ q, const float* __restrict__ tk,
              const float* __restrict__ tv)
{
    const int bid = blockIdx.x, tid = threadIdx.x;
    const int lr = tid >> 6, k = tid & 63;

    if (bid < 16384){                       // ---- KD ----
        int gr = bid*4 + lr;
        int s = gr >> 8, r = gr & 255;
        float d = 0.f;
        if (r < 255){
            int rp = r+1, e = 31-__clz(rp), pj = rp-(1<<e);
            int j = e ? (int)(__brev((unsigned)pj) >> (32-e)) : 0;
            size_t node = (((size_t)1<<(e+8))-1) + (size_t)s*(1<<e) + j;
            d = tk[node*128 + k] - tk[node*128 + 64 + k];
        }
        __nv_bfloat16 h, lo; split2(d, h, lo);
        g_kdh[(size_t)gr*72 + k] = h; g_kdl[(size_t)gr*72 + k] = lo;
    } else if (bid < 32768){                // ---- V ----
        int gr = (bid - 16384)*4 + lr;
        int s = gr >> 8, r = gr & 255;
        size_t leaf = (size_t)s*256 + (__brev((unsigned)r) >> 24);
        float v = tv[leaf*64 + k];
        __nv_bfloat16 h, lo; split2(v, h, lo);
        g_vh[(size_t)gr*72 + k] = h; g_vl[(size_t)gr*72 + k] = lo;
    } else if (bid < 33280){                // ---- Q ----
        int b = (bid - 32768)*4 + lr;
        __nv_bfloat16 h, lo; split2(q[(size_t)b*64 + k], h, lo);
        g_qh[(size_t)b*72 + k] = h; g_ql[(size_t)b*72 + k] = lo;
    } else {                                // ---- PLOG ----
        extern __shared__ float ps[];
        float* qs = ps;                     // [k][b] stride 65
        float* ks = ps + 64*65;             // [j][k] 16 nodes
        int pb = bid - 33280;
        int btile = pb >> 4, slice = pb & 15;
        int b_base = btile * 64, n0 = slice * 16;
        for (int i = tid; i < 64*64; i += 256){
            int b = i >> 6, kk = i & 63;
            qs[kk*65 + b] = q[(size_t)(b_base + b)*64 + kk];
        }
        for (int i = tid; i < 16*64; i += 256){
            int j = i >> 6, kk = i & 63;
            int n = n0 + j;
            ks[i] = (n < 255) ? (tk[(size_t)n*128 + kk] - tk[(size_t)n*128 + 64 + kk]) : 0.f;
        }
        __syncthreads();
        int b = tid & 63, sub = tid >> 6;
        #pragma unroll
        for (int j2 = 0; j2 < 4; j2++){
            int j = sub*4 + j2, n = n0 + j;
            if (n >= 255) break;
            float acc = 0.f;
            #pragma unroll 16
            for (int kk = 0; kk < 64; kk++)
                acc = fmaf(qs[kk*65 + b], ks[j*64 + kk], acc);
            g_plog[(size_t)n*2048 + b_base + b] = acc;
        }
    }
}

// ----------------------------- main kernel -----------------------------
// BT=128, 512 threads (16 warps: 4 row-groups x 4 col-groups, 32x16 tiles).
// T: slot-major float[257][136]. Level 7 packs split-bf16 leaf pairs in
// place via slotH. Q frags (both planes) in registers.
__global__ __launch_bounds__(512, 1)
void tree_kernel(float* __restrict__ out)
{
    extern __shared__ char smc[];
    float* fT = (float*)smc;
    uint32_t* uT = (uint32_t*)smc;
    float* fPB = (float*)(smc + SB_PB);
    const uint32_t SB = cvta(smc);
    const int tid = threadIdx.x, w = tid >> 5, l = tid & 31;
    const int btile = blockIdx.x, sg = blockIdx.y;
    const int b_base = btile * 128;
    const int rg = w >> 2, cg = w & 3;       // 4 row-groups x 4 col-groups
    const int total = NS * 8;

    auto issue = [&](int t){
        if (t >= total) return;
        int c = t & 7, si = t >> 3;
        size_t off = ((size_t)(sg*NS + si)*256 + (size_t)(c & 3)*64)*72;
        const __nv_bfloat16 *ph = (c < 4) ? g_kdh + off : g_vh + off;
        const __nv_bfloat16 *pl = (c < 4) ? g_kdl + off : g_vl + off;
        uint32_t dst = SB + SB_BUF + (uint32_t)(t & 1)*18432;
        for (int i = tid; i < 576; i += 512){
            cp16(dst + i*16,        (const char*)ph + i*16);
            cp16(dst + 9216 + i*16, (const char*)pl + i*16);
        }
        CP_COMMIT();
    };

    issue(0); issue(1);

    // ---- Q fragments -> registers (2 row tiles of 16 within the 32-row group) ----
    uint32_t QAh[2][4][4], QAl[2][4][4];
    #pragma unroll
    for (int rt = 0; rt < 2; rt++){
        int r0 = b_base + rg*32 + rt*16 + (l >> 2);
        int c0 = 2 * (l & 3);
        #pragma unroll
        for (int kt = 0; kt < 4; kt++){
            int k0 = kt*16 + c0;
            QAh[rt][kt][0] = *(const uint32_t*)&g_qh[(size_t)r0*72 + k0];
            QAh[rt][kt][1] = *(const uint32_t*)&g_qh[(size_t)(r0+8)*72 + k0];
            QAh[rt][kt][2] = *(const uint32_t*)&g_qh[(size_t)r0*72 + k0 + 8];
            QAh[rt][kt][3] = *(const uint32_t*)&g_qh[(size_t)(r0+8)*72 + k0 + 8];
            QAl[rt][kt][0] = *(const uint32_t*)&g_ql[(size_t)r0*72 + k0];
            QAl[rt][kt][1] = *(const uint32_t*)&g_ql[(size_t)(r0+8)*72 + k0];
            QAl[rt][kt][2] = *(const uint32_t*)&g_ql[(size_t)r0*72 + k0 + 8];
            QAl[rt][kt][3] = *(const uint32_t*)&g_ql[(size_t)(r0+8)*72 + k0 + 8];
        }
    }

    // ---- 9 path logits per batch -> base probs ----
    for (int i = tid; i < 9*128; i += 512){
        int n = i >> 7, b = i & 127;
        int node = (n < 7) ? ((1 << n) - 1 + (sg >> (6 - n)))
                           : (127 + 2*sg + (n - 7));
        fT[n*TS + b] = g_plog[(size_t)node*2048 + b_base + b];
    }
    __syncthreads();
    if (tid < 128){
        int b = tid;
        float common = 1.f;
        #pragma unroll
        for (int e = 0; e < 6; e++){
            int bit = (sg >> (5 - e)) & 1;
            float x = fT[e*TS + b];
            common *= fast_sigmoid(bit ? -x : x);
        }
        float s6  = fast_sigmoid(fT[6*TS + b]);
        float s7a = fast_sigmoid(fT[7*TS + b]);
        float s7b = fast_sigmoid(fT[8*TS + b]);
        fPB[0*128 + b] = common * s6 * s7a;
        fPB[1*128 + b] = common * s6 * (1.f - s7a);
        fPB[2*128 + b] = common * (1.f - s6) * s7b;
        fPB[3*128 + b] = common * (1.f - s6) * (1.f - s7b);
    }

    float acc2[2][2][4];
    #pragma unroll
    for (int rt = 0; rt < 2; rt++)
        #pragma unroll
        for (int i = 0; i < 2; i++)
            #pragma unroll
            for (int j = 0; j < 4; j++) acc2[rt][i][j] = 0.f;

    for (int si = 0; si < NS; si++){
        // ---------------- GEMM1: 4 passes of 64 n-columns ----------------
        for (int p = 0; p < 4; p++){
            int t = si*8 + p;
            if (t + 1 < total) CP_WAIT(1); else CP_WAIT(0);
            __syncthreads();
            uint32_t kb = SB + SB_BUF + (uint32_t)(t & 1)*18432;
            float a1[2][2][4];
            #pragma unroll
            for (int rt = 0; rt < 2; rt++)
                #pragma unroll
                for (int i = 0; i < 2; i++)
                    #pragma unroll
                    for (int j = 0; j < 4; j++) a1[rt][i][j] = 0.f;
            #pragma unroll
            for (int kt = 0; kt < 4; kt++){
                uint32_t bo = kb + (uint32_t)((
                    (cg*16 + (((l >> 4) & 1) << 3) + (l & 7))*72
                    + kt*16 + (((l >> 3) & 1) << 3)) << 1);
                uint32_t Bh[4], Bl[4];
                ldsm4(Bh, bo); ldsm4(Bl, bo + 9216);
                #pragma unroll
                for (int rt = 0; rt < 2; rt++){
                    mma(a1[rt][0], QAh[rt][kt], Bh[0], Bh[1]);
                    mma(a1[rt][0], QAh[rt][kt], Bl[0], Bl[1]);
                    mma(a1[rt][0], QAl[rt][kt], Bh[0], Bh[1]);
                    mma(a1[rt][1], QAh[rt][kt], Bh[2], Bh[3]);
                    mma(a1[rt][1], QAh[rt][kt], Bl[2], Bl[3]);
                    mma(a1[rt][1], QAl[rt][kt], Bh[2], Bh[3]);
                }
            }
            // sigma fused: store into slot-major T [1+node][b]
            #pragma unroll
            for (int rt = 0; rt < 2; rt++)
                #pragma unroll
                for (int nt = 0; nt < 2; nt++){
                    int r = rg*32 + rt*16 + (l >> 2);
                    int cc = p*64 + cg*16 + nt*8 + 2*(l & 3);
                    fT[(1 + cc)*TS + r]     = fast_sigmoid(a1[rt][nt][0]);
                    fT[(2 + cc)*TS + r]     = fast_sigmoid(a1[rt][nt][1]);
                    fT[(1 + cc)*TS + r + 8] = fast_sigmoid(a1[rt][nt][2]);
                    fT[(2 + cc)*TS + r + 8] = fast_sigmoid(a1[rt][nt][3]);
                }
            __syncthreads();
            if (t + 2 < total) issue(t + 2);
        }
        if (tid < 128) fT[tid] = fPB[si*128 + tid];   // slot 0
        __syncthreads();

        // ------- expansion: fused triple levels, warp-private 8 batches -------
        {
            const int wb = w * 8;
            // step A: levels 0,1,2 (1 parent -> 8); lanes 0-3
            if (l < 4){
                int b2 = wb + 2*l;
                float2 v   = *(float2*)&fT[0*TS + b2];
                float2 s0  = *(float2*)&fT[1*TS + b2];
                float2 s10 = *(float2*)&fT[2*TS + b2];
                float2 s11 = *(float2*)&fT[3*TS + b2];
                float2 s2[4];
                #pragma unroll
                for (int j = 0; j < 4; j++) s2[j] = *(float2*)&fT[(4+j)*TS + b2];
                float2 a0{v.x*s0.x, v.y*s0.y}, a1v{v.x-a0.x, v.y-a0.y};
                float2 bb[4];
                bb[0] = {a0.x*s10.x,  a0.y*s10.y};  bb[2] = {a0.x-bb[0].x,  a0.y-bb[0].y};
                bb[1] = {a1v.x*s11.x, a1v.y*s11.y}; bb[3] = {a1v.x-bb[1].x, a1v.y-bb[1].y};
                #pragma unroll
                for (int j = 0; j < 4; j++){
                    float2 c0{bb[j].x*s2[j].x, bb[j].y*s2[j].y};
                    float2 c1{bb[j].x-c0.x,    bb[j].y-c0.y};
                    *(float2*)&fT[j*TS + b2]     = c0;
                    *(float2*)&fT[(j+4)*TS + b2] = c1;
                }
            }
            __syncwarp();
            // step B: levels 3,4,5 (8 parents -> 64); 32 items
            {
                int pos = l >> 2, b2 = wb + 2*(l & 3);
                float2 v   = *(float2*)&fT[pos*TS + b2];
                float2 s3  = *(float2*)&fT[(8+pos)*TS + b2];
                float2 s40 = *(float2*)&fT[(16+pos)*TS + b2];
                float2 s41 = *(float2*)&fT[(24+pos)*TS + b2];
                float2 s5[4];
                #pragma unroll
                for (int j = 0; j < 4; j++) s5[j] = *(float2*)&fT[(32+8*j+pos)*TS + b2];
                float2 a0{v.x*s3.x, v.y*s3.y}, a1v{v.x-a0.x, v.y-a0.y};
                float2 bb[4];
                bb[0] = {a0.x*s40.x,  a0.y*s40.y};  bb[2] = {a0.x-bb[0].x,  a0.y-bb[0].y};
                bb[1] = {a1v.x*s41.x, a1v.y*s41.y}; bb[3] = {a1v.x-bb[1].x, a1v.y-bb[1].y};
                #pragma unroll
                for (int j = 0; j < 4; j++){
                    float2 c0{bb[j].x*s5[j].x, bb[j].y*s5[j].y};
                    float2 c1{bb[j].x-c0.x,    bb[j].y-c0.y};
                    *(float2*)&fT[(8*j+pos)*TS + b2]    = c0;
                    *(float2*)&fT[(32+8*j+pos)*TS + b2] = c1;
                }
            }
            __syncwarp();
            // level 6 (64 parents -> 128); 256 items
            for (int it = l; it < 256; it += 32){
                int pos = it >> 2, b2 = wb + 2*(it & 3);
                float2 v = *(float2*)&fT[pos*TS + b2];
                float2 s = *(float2*)&fT[(64+pos)*TS + b2];
                float2 c0{v.x*s.x, v.y*s.y};
                float2 c1{v.x-c0.x, v.y-c0.y};
                *(float2*)&fT[pos*TS + b2]      = c0;
                *(float2*)&fT[(64+pos)*TS + b2] = c1;
            }
            __syncwarp();
            // level 7 + split-pack (permuted slots); 256 items
            for (int it = l; it < 256; it += 32){
                int pp = it >> 2, b2 = wb + 2*(it & 3);
                float2 v0 = *(float2*)&fT[(2*pp)*TS + b2];
                float2 v1 = *(float2*)&fT[(2*pp+1)*TS + b2];
                float2 s0 = *(float2*)&fT[(128+2*pp)*TS + b2];
                float2 s1 = *(float2*)&fT[(129+2*pp)*TS + b2];
                float c0ax = v0.x*s0.x, c1ax = v0.x-c0ax;
                float c0bx = v1.x*s1.x, c1bx = v1.x-c0bx;
                float c0ay = v0.y*s0.y, c1ay = v0.y-c0ay;
                float c0by = v1.y*s1.y, c1by = v1.y-c0by;
                uint32_t h1x,l1x,h2x,l2x,h1y,l1y,h2y,l2y;
                splitpair(c0ax, c0bx, h1x, l1x);
                splitpair(c1ax, c1bx, h2x, l2x);
                splitpair(c0ay, c0by, h1y, l1y);
                splitpair(c1ay, c1by, h2y, l2y);
                int tt = (pp >> 1) & 1;
                int s1h = 2*pp + tt, s2h = 2*pp + 1 - tt;
                *(uint2*)&uT[s1h*TS + b2]       = make_uint2(h1x, h1y);
                *(uint2*)&uT[s2h*TS + b2]       = make_uint2(h2x, h2y);
                *(uint2*)&uT[(s1h+128)*TS + b2] = make_uint2(l1x, l1y);
                *(uint2*)&uT[(s2h+128)*TS + b2] = make_uint2(l2x, l2y);
            }
        }
        __syncthreads();

        // ---------------- GEMM2: 4 k-chunks, register accumulator ----------------
        for (int c = 0; c < 4; c++){
            int t = si*8 + 4 + c;
            if (t + 1 < total) CP_WAIT(1); else CP_WAIT(0);
            __syncthreads();
            uint32_t vb = SB + SB_BUF + (uint32_t)(t & 1)*18432;
            #pragma unroll
            for (int kt = 0; kt < 4; kt++){
                int Pb = c*32 + kt*8;
                int Pa = Pb + (l & 3), Pc = Pb + 4 + (l & 3);
                int sa = slotH(Pa), sc = slotH(Pc);
                uint32_t Ah[2][4], Al[2][4];
                #pragma unroll
                for (int rt = 0; rt < 2; rt++){
                    int r0 = rg*32 + rt*16 + (l >> 2);
                    Ah[rt][0] = uT[sa*TS + r0];
                    Ah[rt][1] = uT[sa*TS + r0 + 8];
                    Ah[rt][2] = uT[sc*TS + r0];
                    Ah[rt][3] = uT[sc*TS + r0 + 8];
                    Al[rt][0] = uT[(sa+128)*TS + r0];
                    Al[rt][1] = uT[(sa+128)*TS + r0 + 8];
                    Al[rt][2] = uT[(sc+128)*TS + r0];
                    Al[rt][3] = uT[(sc+128)*TS + r0 + 8];
                }
                uint32_t bo = vb + (uint32_t)((
                    (kt*16 + (((l >> 3) & 1) << 3) + (l & 7))*72
                    + cg*16 + (((l >> 4) & 1) << 3)) << 1);
                uint32_t Bh[4], Bl[4];
                ldsm4t(Bh, bo); ldsm4t(Bl, bo + 9216);
                #pragma unroll
                for (int rt = 0; rt < 2; rt++){
                    mma(acc2[rt][0], Ah[rt], Bh[0], Bh[1]);
                    mma(acc2[rt][0], Ah[rt], Bl[0], Bl[1]);
                    mma(acc2[rt][0], Al[rt], Bh[0], Bh[1]);
                    mma(acc2[rt][1], Ah[rt], Bh[2], Bh[3]);
                    mma(acc2[rt][1], Ah[rt], Bl[2], Bl[3]);
                    mma(acc2[rt][1], Al[rt], Bh[2], Bh[3]);
                }
            }
            __syncthreads();
            if (t + 2 < total) issue(t + 2);
        }
    }

    // ---------------- epilogue: one atomic pass per CTA ----------------
    #pragma unroll
    for (int rt = 0; rt < 2; rt++)
        #pragma unroll
        for (int dt = 0; dt < 2; dt++){
            int r = b_base + rg*32 + rt*16 + (l >> 2);
            int cc = cg*16 + dt*8 + 2*(l & 3);
            atomicAdd(&out[(size_t)r*64 + cc],         acc2[rt][dt][0]);
            atomicAdd(&out[(size_t)r*64 + cc + 1],     acc2[rt][dt][1]);
            atomicAdd(&out[(size_t)(r+8)*64 + cc],     acc2[rt][dt][2]);
            atomicAdd(&out[(size_t)(r+8)*64 + cc + 1], acc2[rt][dt][3]);
        }
}

extern "C" void kernel_launch(void* const* d_in, const int* in_sizes, int n_in,
                              void* d_out, int out_size) {
    const float* q  = (const float*)d_in[0];
    const float* tk = (const float*)d_in[1];
    const float* tv = (const float*)d_in[2];
    float* out = (float*)d_out;

    cudaFuncSetAttribute(tree_kernel,
                         cudaFuncAttributeMaxDynamicSharedMemorySize, SMEM_BYTES);

    cudaMemsetAsync(out, 0, (size_t)2048 * 64 * sizeof(float));
    prep_all<<<33792, 256, PLOG_SMEM>>>(q, tk, tv);
    tree_kernel<<<dim3(16, 64), 512, SMEM_BYTES>>>(out);
}

// round 16
// speedup vs baseline: 1.0801x; 1.0681x over previous
#include <cuda_runtime.h>
#include <cuda_bf16.h>
#include <cstdint>

#define NS 4
// smem (bytes): T = float[257 slots][72], 2 chunk bufs, base-prob scratch
#define SB_BUF  74016              // T = 257*72*4
#define SB_PB   110880             // float[4*64]
#define SMEM_BYTES 111904          // 2 CTAs/SM
#define PLOG_SMEM ((64*65 + 16*64) * 4)   // 20736

__device__ __align__(256) __nv_bfloat16 g_kdh[256*256*72];
__device__ __align__(256) __nv_bfloat16 g_kdl[256*256*72];
__device__ __align__(256) __nv_bfloat16 g_vh [256*256*72];
__device__ __align__(256) __nv_bfloat16 g_vl [256*256*72];
__device__ __align__(256) __nv_bfloat16 g_qh [2048*72];
__device__ __align__(256) __nv_bfloat16 g_ql [2048*72];
__device__ float g_plog[255*2048];

__device__ __forceinline__ uint32_t cvta(const void* p){
    uint32_t a; asm("{.reg .u64 t; cvta.to.shared.u64 t,%1; cvt.u32.u64 %0,t;}":"=r"(a):"l"(p)); return a;
}
__device__ __forceinline__ void ldsm4(uint32_t r[4], uint32_t a){
    asm volatile("ldmatrix.sync.aligned.m8n8.x4.shared.b16 {%0,%1,%2,%3},[%4];"
        :"=r"(r[0]),"=r"(r[1]),"=r"(r[2]),"=r"(r[3]):"r"(a));
}
__device__ __forceinline__ void ldsm4t(uint32_t r[4], uint32_t a){
    asm volatile("ldmatrix.sync.aligned.m8n8.x4.trans.shared.b16 {%0,%1,%2,%3},[%4];"
        :"=r"(r[0]),"=r"(r[1]),"=r"(r[2]),"=r"(r[3]):"r"(a));
}
__device__ __forceinline__ void mma(float c[4], const uint32_t a[4], const uint32_t b0, const uint32_t b1){
    asm volatile("mma.sync.aligned.m16n8k16.row.col.f32.bf16.bf16.f32 "
        "{%0,%1,%2,%3},{%4,%5,%6,%7},{%8,%9},{%0,%1,%2,%3};"
        :"+f"(c[0]),"+f"(c[1]),"+f"(c[2]),"+f"(c[3])
        :"r"(a[0]),"r"(a[1]),"r"(a[2]),"r"(a[3]),"r"(b0),"r"(b1));
}
__device__ __forceinline__ void cp16(uint32_t d, const void* s){
    asm volatile("cp.async.cg.shared.global [%0],[%1],16;"::"r"(d),"l"(s));
}
#define CP_COMMIT() asm volatile("cp.async.commit_group;":::"memory")
#define CP_WAIT(N)  asm volatile("cp.async.wait_group %0;"::"n"(N):"memory")
__device__ __forceinline__ void split2(float x, __nv_bfloat16& h, __nv_bfloat16& lo){
    h = __float2bfloat16(x); lo = __float2bfloat16(x - __bfloat162float(h));
}
__device__ __forceinline__ void splitpair(float a, float b, uint32_t& hw, uint32_t& lw){
    __nv_bfloat16 ha, la, hb, lb;
    split2(a, ha, la); split2(b, hb, lb);
    hw = (uint32_t)__bfloat16_as_ushort(ha) | ((uint32_t)__bfloat16_as_ushort(hb) << 16);
    lw = (uint32_t)__bfloat16_as_ushort(la) | ((uint32_t)__bfloat16_as_ushort(lb) << 16);
}
__device__ __forceinline__ float fast_sigmoid(float x){
    float e; asm("ex2.approx.f32 %0,%1;":"=f"(e):"f"(-x*1.4426950408889634f));
    float r; asm("rcp.approx.f32 %0,%1;":"=f"(r):"f"(1.f+e));
    return r;
}
__device__ __forceinline__ int slotH(int P){
    return (P < 64) ? (2*P + ((P >> 1) & 1))
                    : (2*(P - 64) + 1 - (((P - 64) >> 1) & 1));
}

// ------------------- fused prep: KD | V | Q | PLOG -------------------
__global__ __launch_bounds__(256)
void prep_all(const float* __restrict__ q, const float* __restrict__ tk,
              const float* __restrict__ tv)
{
    const int bid = blockIdx.x, tid = threadIdx.x;
    const int lr = tid >> 6, k = tid & 63;

    if (bid < 16384){                       // ---- KD ----
        int gr = bid*4 + lr;
        int s = gr >> 8, r = gr & 255;
        float d = 0.f;
        if (r < 255){
            int rp = r+1, e = 31-__clz(rp), pj = rp-(1<<e);
            int j = e ? (int)(__brev((unsigned)pj) >> (32-e)) : 0;
            size_t node = (((size_t)1<<(e+8))-1) + (size_t)s*(1<<e) + j;
            d = tk[node*128 + k] - tk[node*128 + 64 + k];
        }
        __nv_bfloat16 h, lo; split2(d, h, lo);
        g_kdh[(size_t)gr*72 + k] = h; g_kdl[(size_t)gr*72 + k] = lo;
    } else if (bid < 32768){                // ---- V ----
        int gr = (bid - 16384)*4 + lr;
        int s = gr >> 8, r = gr & 255;
        size_t leaf = (size_t)s*256 + (__brev((unsigned)r) >> 24);
        float v = tv[leaf*64 + k];
        __nv_bfloat16 h, lo; split2(v, h, lo);
        g_vh[(size_t)gr*72 + k] = h; g_vl[(size_t)gr*72 + k] = lo;
    } else if (bid < 33280){                // ---- Q ----
        int b = (bid - 32768)*4 + lr;
        __nv_bfloat16 h, lo; split2(q[(size_t)b*64 + k], h, lo);
        g_qh[(size_t)b*72 + k] = h; g_ql[(size_t)b*72 + k] = lo;
    } else {                                // ---- PLOG ----
        extern __shared__ float ps[];
        float* qs = ps;                     // [k][b] stride 65
        float* ks = ps + 64*65;             // [j][k] 16 nodes
        int pb = bid - 33280;
        int btile = pb >> 4, slice = pb & 15;
        int b_base = btile * 64, n0 = slice * 16;
        for (int i = tid; i < 64*64; i += 256){
            int b = i >> 6, kk = i & 63;
            qs[kk*65 + b] = q[(size_t)(b_base + b)*64 + kk];
        }
        for (int i = tid; i < 16*64; i += 256){
            int j = i >> 6, kk = i & 63;
            int n = n0 + j;
            ks[i] = (n < 255) ? (tk[(size_t)n*128 + kk] - tk[(size_t)n*128 + 64 + kk]) : 0.f;
        }
        __syncthreads();
        int b = tid & 63, sub = tid >> 6;
        #pragma unroll
        for (int j2 = 0; j2 < 4; j2++){
            int j = sub*4 + j2, n = n0 + j;
            if (n >= 255) break;
            float acc = 0.f;
            #pragma unroll 16
            for (int kk = 0; kk < 64; kk++)
                acc = fmaf(qs[kk*65 + b], ks[j*64 + kk], acc);
            g_plog[(size_t)n*2048 + b_base + b] = acc;
        }
    }
}

// ----------------------------- main kernel -----------------------------
// T: slot-major float[257][72]. slot 0 = base prob; slot 2^e+pos = sigma of
// expansion level e; cum(pos) at slot pos. Level 7 packs split-bf16 leaf
// pairs in place via slotH (bank-decorrelated).
__global__ __launch_bounds__(256, 2)
void tree_kernel(float* __restrict__ out)
{
    extern __shared__ char smc[];
    float* fT = (float*)smc;
    uint32_t* uT = (uint32_t*)smc;
    float* fPB = (float*)(smc + SB_PB);
    const uint32_t SB = cvta(smc);
    const int tid = threadIdx.x, w = tid >> 5, l = tid & 31;
    const int btile = blockIdx.x, sg = blockIdx.y;
    const int b_base = btile * 64;
    const int bt = w & 3, grp = w >> 2;
    const int total = NS * 8;

    auto issue = [&](int t){
        if (t >= total) return;
        int c = t & 7, si = t >> 3;
        size_t off = ((size_t)(sg*NS + si)*256 + (size_t)(c & 3)*64)*72;
        const __nv_bfloat16 *ph = (c < 4) ? g_kdh + off : g_vh + off;
        const __nv_bfloat16 *pl = (c < 4) ? g_kdl + off : g_vl + off;
        uint32_t dst = SB + SB_BUF + (uint32_t)(t & 1)*18432;
        for (int i = tid; i < 576; i += 256){
            cp16(dst + i*16,        (const char*)ph + i*16);
            cp16(dst + 9216 + i*16, (const char*)pl + i*16);
        }
        CP_COMMIT();
    };

    issue(0); issue(1);

    // ---- Q fragments -> registers ----
    uint32_t QAh[4][4], QAl[4][4];
    {
        int r0 = b_base + bt*16 + (l >> 2);
        int c0 = 2 * (l & 3);
        #pragma unroll
        for (int kt = 0; kt < 4; kt++){
            int k0 = kt*16 + c0;
            QAh[kt][0] = *(const uint32_t*)&g_qh[(size_t)r0*72 + k0];
            QAh[kt][1] = *(const uint32_t*)&g_qh[(size_t)(r0+8)*72 + k0];
            QAh[kt][2] = *(const uint32_t*)&g_qh[(size_t)r0*72 + k0 + 8];
            QAh[kt][3] = *(const uint32_t*)&g_qh[(size_t)(r0+8)*72 + k0 + 8];
            QAl[kt][0] = *(const uint32_t*)&g_ql[(size_t)r0*72 + k0];
            QAl[kt][1] = *(const uint32_t*)&g_ql[(size_t)(r0+8)*72 + k0];
            QAl[kt][2] = *(const uint32_t*)&g_ql[(size_t)r0*72 + k0 + 8];
            QAl[kt][3] = *(const uint32_t*)&g_ql[(size_t)(r0+8)*72 + k0 + 8];
        }
    }

    // ---- 9 path logits per batch -> base probs ----
    for (int i = tid; i < 9*64; i += 256){
        int n = i >> 6, b = i & 63;
        int node = (n < 7) ? ((1 << n) - 1 + (sg >> (6 - n)))
                           : (127 + 2*sg + (n - 7));
        fT[n*64 + b] = g_plog[(size_t)node*2048 + b_base + b];
    }
    __syncthreads();
    if (tid < 64){
        int b = tid;
        float common = 1.f;
        #pragma unroll
        for (int e = 0; e < 6; e++){
            int bit = (sg >> (5 - e)) & 1;
            float x = fT[e*64 + b];
            common *= fast_sigmoid(bit ? -x : x);
        }
        float s6  = fast_sigmoid(fT[6*64 + b]);
        float s7a = fast_sigmoid(fT[7*64 + b]);
        float s7b = fast_sigmoid(fT[8*64 + b]);
        fPB[0*64 + b] = common * s6 * s7a;
        fPB[1*64 + b] = common * s6 * (1.f - s7a);
        fPB[2*64 + b] = common * (1.f - s6) * s7b;
        fPB[3*64 + b] = common * (1.f - s6) * (1.f - s7b);
    }

    float acc2[4][4];
    #pragma unroll
    for (int i = 0; i < 4; i++)
        #pragma unroll
        for (int j = 0; j < 4; j++) acc2[i][j] = 0.f;

    for (int si = 0; si < NS; si++){
        // ---------------- GEMM1: 4 passes of 64 n-columns ----------------
        for (int p = 0; p < 4; p++){
            int t = si*8 + p;
            if (t + 1 < total) CP_WAIT(1); else CP_WAIT(0);
            __syncthreads();
            uint32_t kb = SB + SB_BUF + (uint32_t)(t & 1)*18432;
            float a1[4][4];
            #pragma unroll
            for (int i = 0; i < 4; i++)
                #pragma unroll
                for (int j = 0; j < 4; j++) a1[i][j] = 0.f;
            #pragma unroll
            for (int kt = 0; kt < 4; kt++){
                #pragma unroll
                for (int ntp = 0; ntp < 2; ntp++){
                    uint32_t bo = kb + (uint32_t)((
                        (grp*32 + ntp*16 + (((l >> 4) & 1) << 3) + (l & 7))*72
                        + kt*16 + (((l >> 3) & 1) << 3)) << 1);
                    uint32_t Bh[4], Bl[4];
                    ldsm4(Bh, bo); ldsm4(Bl, bo + 9216);
                    mma(a1[2*ntp],   QAh[kt], Bh[0], Bh[1]);
                    mma(a1[2*ntp],   QAh[kt], Bl[0], Bl[1]);
                    mma(a1[2*ntp],   QAl[kt], Bh[0], Bh[1]);
                    mma(a1[2*ntp+1], QAh[kt], Bh[2], Bh[3]);
                    mma(a1[2*ntp+1], QAh[kt], Bl[2], Bl[3]);
                    mma(a1[2*ntp+1], QAl[kt], Bh[2], Bh[3]);
                }
            }
            // sigma fused; lane-pair swizzled store order -> conflict-free STS
            {
                int o1 = (l >> 1) & 1;
                #pragma unroll
                for (int nt = 0; nt < 4; nt++){
                    int r = bt*16 + (l >> 2);
                    int cc = p*64 + grp*32 + nt*8 + 2*(l & 3);
                    fT[(1 + cc + o1)*72 + r]           = fast_sigmoid(a1[nt][o1]);
                    fT[(1 + cc + (1 - o1))*72 + r]     = fast_sigmoid(a1[nt][1 - o1]);
                    fT[(1 + cc + o1)*72 + r + 8]       = fast_sigmoid(a1[nt][2 + o1]);
                    fT[(1 + cc + (1 - o1))*72 + r + 8] = fast_sigmoid(a1[nt][3 - o1]);
                }
            }
            __syncthreads();
            if (t + 2 < total) issue(t + 2);
        }
        if (tid < 64) fT[tid] = fPB[si*64 + tid];   // slot 0
        __syncthreads();

        // ------- expansion: fused triple levels, in-place -------
        {
            const int wb = w * 8;
            // step A: levels 0,1,2 (1 parent -> 8); lanes 0-3
            if (l < 4){
                int b2 = wb + 2*l;
                float2 v   = *(float2*)&fT[0*72 + b2];
                float2 s0  = *(float2*)&fT[1*72 + b2];
                float2 s10 = *(float2*)&fT[2*72 + b2];
                float2 s11 = *(float2*)&fT[3*72 + b2];
                float2 s2[4];
                #pragma unroll
                for (int j = 0; j < 4; j++) s2[j] = *(float2*)&fT[(4+j)*72 + b2];
                float2 a0{v.x*s0.x, v.y*s0.y}, a1v{v.x-a0.x, v.y-a0.y};
                float2 bb[4];
                bb[0] = {a0.x*s10.x,  a0.y*s10.y};  bb[2] = {a0.x-bb[0].x,  a0.y-bb[0].y};
                bb[1] = {a1v.x*s11.x, a1v.y*s11.y}; bb[3] = {a1v.x-bb[1].x, a1v.y-bb[1].y};
                #pragma unroll
                for (int j = 0; j < 4; j++){
                    float2 c0{bb[j].x*s2[j].x, bb[j].y*s2[j].y};
                    float2 c1{bb[j].x-c0.x,    bb[j].y-c0.y};
                    *(float2*)&fT[j*72 + b2]     = c0;
                    *(float2*)&fT[(j+4)*72 + b2] = c1;
                }
            }
            __syncwarp();
            // step B: levels 3,4,5 (8 parents -> 64); 32 lanes
            {
                int pos = l >> 2, b2 = wb + 2*(l & 3);
                float2 v   = *(float2*)&fT[pos*72 + b2];
                float2 s3  = *(float2*)&fT[(8+pos)*72 + b2];
                float2 s40 = *(float2*)&fT[(16+pos)*72 + b2];
                float2 s41 = *(float2*)&fT[(24+pos)*72 + b2];
                float2 s5[4];
                #pragma unroll
                for (int j = 0; j < 4; j++) s5[j] = *(float2*)&fT[(32+8*j+pos)*72 + b2];
                float2 a0{v.x*s3.x, v.y*s3.y}, a1v{v.x-a0.x, v.y-a0.y};
                float2 bb[4];
                bb[0] = {a0.x*s40.x,  a0.y*s40.y};  bb[2] = {a0.x-bb[0].x,  a0.y-bb[0].y};
                bb[1] = {a1v.x*s41.x, a1v.y*s41.y}; bb[3] = {a1v.x-bb[1].x, a1v.y-bb[1].y};
                #pragma unroll
                for (int j = 0; j < 4; j++){
                    float2 c0{bb[j].x*s5[j].x, bb[j].y*s5[j].y};
                    float2 c1{bb[j].x-c0.x,    bb[j].y-c0.y};
                    *(float2*)&fT[(8*j+pos)*72 + b2]    = c0;
                    *(float2*)&fT[(32+8*j+pos)*72 + b2] = c1;
                }
            }
            __syncwarp();
            // level 6 (64 parents -> 128); float4 over 4-batch quads
            #pragma unroll
            for (int ii = 0; ii < 4; ii++){
                int it = l + ii*32;
                int pos = it >> 1, b4 = wb + 4*(it & 1);
                float4 v = *(float4*)&fT[pos*72 + b4];
                float4 s = *(float4*)&fT[(64+pos)*72 + b4];
                float4 c0{v.x*s.x, v.y*s.y, v.z*s.z, v.w*s.w};
                float4 c1{v.x-c0.x, v.y-c0.y, v.z-c0.z, v.w-c0.w};
                *(float4*)&fT[pos*72 + b4]      = c0;
                *(float4*)&fT[(64+pos)*72 + b4] = c1;
            }
            __syncwarp();
            // level 7 + split-pack (permuted slots); float4/uint4 quads
            #pragma unroll
            for (int ii = 0; ii < 4; ii++){
                int it = l + ii*32;
                int pp = it >> 1, b4 = wb + 4*(it & 1);
                float4 v0 = *(float4*)&fT[(2*pp)*72 + b4];
                float4 v1 = *(float4*)&fT[(2*pp+1)*72 + b4];
                float4 s0 = *(float4*)&fT[(128+2*pp)*72 + b4];
                float4 s1 = *(float4*)&fT[(129+2*pp)*72 + b4];
                float4 c0a{v0.x*s0.x, v0.y*s0.y, v0.z*s0.z, v0.w*s0.w};
                float4 c1a{v0.x-c0a.x, v0.y-c0a.y, v0.z-c0a.z, v0.w-c0a.w};
                float4 c0b{v1.x*s1.x, v1.y*s1.y, v1.z*s1.z, v1.w*s1.w};
                float4 c1b{v1.x-c0b.x, v1.y-c0b.y, v1.z-c0b.z, v1.w-c0b.w};
                uint4 H1, H2, L1, L2;
                splitpair(c0a.x, c0b.x, H1.x, L1.x);
                splitpair(c0a.y, c0b.y, H1.y, L1.y);
                splitpair(c0a.z, c0b.z, H1.z, L1.z);
                splitpair(c0a.w, c0b.w, H1.w, L1.w);
                splitpair(c1a.x, c1b.x, H2.x, L2.x);
                splitpair(c1a.y, c1b.y, H2.y, L2.y);
                splitpair(c1a.z, c1b.z, H2.z, L2.z);
                splitpair(c1a.w, c1b.w, H2.w, L2.w);
                int tt = (pp >> 1) & 1;
                int s1h = 2*pp + tt, s2h = 2*pp + 1 - tt;
                *(uint4*)&uT[s1h*72 + b4]       = H1;
                *(uint4*)&uT[s2h*72 + b4]       = H2;
                *(uint4*)&uT[(s1h+128)*72 + b4] = L1;
                *(uint4*)&uT[(s2h+128)*72 + b4] = L2;
            }
        }
        __syncthreads();

        // ---------------- GEMM2: 4 k-chunks, register accumulator ----------------
        for (int c = 0; c < 4; c++){
            int t = si*8 + 4 + c;
            if (t + 1 < total) CP_WAIT(1); else CP_WAIT(0);
            __syncthreads();
            uint32_t vb = SB + SB_BUF + (uint32_t)(t & 1)*18432;
            #pragma unroll
            for (int kt = 0; kt < 4; kt++){
                int r0 = bt*16 + (l >> 2);
                int Pb = c*32 + kt*8;
                int Pa = Pb + (l & 3), Pc = Pb + 4 + (l & 3);
                int sa = slotH(Pa), sc = slotH(Pc);
                uint32_t Ah[4], Al[4];
                Ah[0] = uT[sa*72 + r0];
                Ah[1] = uT[sa*72 + r0 + 8];
                Ah[2] = uT[sc*72 + r0];
                Ah[3] = uT[sc*72 + r0 + 8];
                Al[0] = uT[(sa+128)*72 + r0];
                Al[1] = uT[(sa+128)*72 + r0 + 8];
                Al[2] = uT[(sc+128)*72 + r0];
                Al[3] = uT[(sc+128)*72 + r0 + 8];
                #pragma unroll
                for (int dtp = 0; dtp < 2; dtp++){
                    uint32_t bo = vb + (uint32_t)((
                        (kt*16 + (((l >> 3) & 1) << 3) + (l & 7))*72
                        + grp*32 + dtp*16 + (((l >> 4) & 1) << 3)) << 1);
                    uint32_t Bh[4], Bl[4];
                    ldsm4t(Bh, bo); ldsm4t(Bl, bo + 9216);
                    mma(acc2[2*dtp],   Ah, Bh[0], Bh[1]);
                    mma(acc2[2*dtp],   Ah, Bl[0], Bl[1]);
                    mma(acc2[2*dtp],   Al, Bh[0], Bh[1]);
                    mma(acc2[2*dtp+1], Ah, Bh[2], Bh[3]);
                    mma(acc2[2*dtp+1], Ah, Bl[2], Bl[3]);
                    mma(acc2[2*dtp+1], Al, Bh[2], Bh[3]);
                }
            }
            __syncthreads();
            if (t + 2 < total) issue(t + 2);
        }
    }

    // ---------------- epilogue: one atomic pass per CTA ----------------
    #pragma unroll
    for (int dt = 0; dt < 4; dt++){
        int r = b_base + bt*16 + (l >> 2);
        int cc = grp*32 + dt*8 + 2*(l & 3);
        atomicAdd(&out[(size_t)r*64 + cc],         acc2[dt][0]);
        atomicAdd(&out[(size_t)r*64 + cc + 1],     acc2[dt][1]);
        atomicAdd(&out[(size_t)(r+8)*64 + cc],     acc2[dt][2]);
        atomicAdd(&out[(size_t)(r+8)*64 + cc + 1], acc2[dt][3]);
    }
}

extern "C" void kernel_launch(void* const* d_in, const int* in_sizes, int n_in,
                              void* d_out, int out_size) {
    const float* q  = (const float*)d_in[0];
    const float* tk = (const float*)d_in[1];
    const float* tv = (const float*)d_in[2];
    float* out = (float*)d_out;

    cudaFuncSetAttribute(tree_kernel,
                         cudaFuncAttributeMaxDynamicSharedMemorySize, SMEM_BYTES);

    cudaMemsetAsync(out, 0, (size_t)2048 * 64 * sizeof(float));
    prep_all<<<33792, 256, PLOG_SMEM>>>(q, tk, tv);
    tree_kernel<<<dim3(32, 64), 256, SMEM_BYTES>>>(out);
}

// round 17
// speedup vs baseline: 1.1659x; 1.0795x over previous
#include <cuda_runtime.h>
#include <cuda_bf16.h>
#include <cstdint>

#define NS 4
// smem (bytes): T = float[257 slots][72], 2 chunk bufs, base-prob scratch
#define SB_BUF  74016              // T = 257*72*4
#define SB_PB   110880             // float[4*64]
#define SMEM_BYTES 111904          // 2 CTAs/SM
#define PLOG_SMEM ((64*65 + 16*64) * 4)   // 20736

__device__ __align__(256) __nv_bfloat16 g_kdh[256*256*72];
__device__ __align__(256) __nv_bfloat16 g_kdl[256*256*72];
__device__ __align__(256) __nv_bfloat16 g_vh [256*256*72];
__device__ __align__(256) __nv_bfloat16 g_vl [256*256*72];
__device__ __align__(256) __nv_bfloat16 g_qh [2048*72];
__device__ __align__(256) __nv_bfloat16 g_ql [2048*72];
__device__ float g_plog[255*2048];

__device__ __forceinline__ uint32_t cvta(const void* p){
    uint32_t a; asm("{.reg .u64 t; cvta.to.shared.u64 t,%1; cvt.u32.u64 %0,t;}":"=r"(a):"l"(p)); return a;
}
__device__ __forceinline__ void ldsm4(uint32_t r[4], uint32_t a){
    asm volatile("ldmatrix.sync.aligned.m8n8.x4.shared.b16 {%0,%1,%2,%3},[%4];"
        :"=r"(r[0]),"=r"(r[1]),"=r"(r[2]),"=r"(r[3]):"r"(a));
}
__device__ __forceinline__ void ldsm4t(uint32_t r[4], uint32_t a){
    asm volatile("ldmatrix.sync.aligned.m8n8.x4.trans.shared.b16 {%0,%1,%2,%3},[%4];"
        :"=r"(r[0]),"=r"(r[1]),"=r"(r[2]),"=r"(r[3]):"r"(a));
}
__device__ __forceinline__ void mma(float c[4], const uint32_t a[4], const uint32_t b0, const uint32_t b1){
    asm volatile("mma.sync.aligned.m16n8k16.row.col.f32.bf16.bf16.f32 "
        "{%0,%1,%2,%3},{%4,%5,%6,%7},{%8,%9},{%0,%1,%2,%3};"
        :"+f"(c[0]),"+f"(c[1]),"+f"(c[2]),"+f"(c[3])
        :"r"(a[0]),"r"(a[1]),"r"(a[2]),"r"(a[3]),"r"(b0),"r"(b1));
}
__device__ __forceinline__ void cp16(uint32_t d, const void* s){
    asm volatile("cp.async.cg.shared.global [%0],[%1],16;"::"r"(d),"l"(s));
}
#define CP_COMMIT() asm volatile("cp.async.commit_group;":::"memory")
#define CP_WAIT(N)  asm volatile("cp.async.wait_group %0;"::"n"(N):"memory")
__device__ __forceinline__ void split2(float x, __nv_bfloat16& h, __nv_bfloat16& lo){
    h = __float2bfloat16(x); lo = __float2bfloat16(x - __bfloat162float(h));
}
__device__ __forceinline__ void splitpair(float a, float b, uint32_t& hw, uint32_t& lw){
    __nv_bfloat16 ha, la, hb, lb;
    split2(a, ha, la); split2(b, hb, lb);
    hw = (uint32_t)__bfloat16_as_ushort(ha) | ((uint32_t)__bfloat16_as_ushort(hb) << 16);
    lw = (uint32_t)__bfloat16_as_ushort(la) | ((uint32_t)__bfloat16_as_ushort(lb) << 16);
}
__device__ __forceinline__ float fast_sigmoid(float x){
    float e; asm("ex2.approx.f32 %0,%1;":"=f"(e):"f"(-x*1.4426950408889634f));
    float r; asm("rcp.approx.f32 %0,%1;":"=f"(r):"f"(1.f+e));
    return r;
}
__device__ __forceinline__ int slotH(int P){
    return (P < 64) ? (2*P + ((P >> 1) & 1))
                    : (2*(P - 64) + 1 - (((P - 64) >> 1) & 1));
}

// ------------------- fused prep: KD | V | Q | PLOG -------------------
__global__ __launch_bounds__(256)
void prep_all(const float* __restrict__ q, const float* __restrict__ tk,
              const float* __restrict__ tv)
{
    const int bid = blockIdx.x, tid = threadIdx.x;
    const int lr = tid >> 6, k = tid & 63;

    if (bid < 16384){                       // ---- KD ----
        int gr = bid*4 + lr;
        int s = gr >> 8, r = gr & 255;
        float d = 0.f;
        if (r < 255){
            int rp = r+1, e = 31-__clz(rp), pj = rp-(1<<e);
            int j = e ? (int)(__brev((unsigned)pj) >> (32-e)) : 0;
            size_t node = (((size_t)1<<(e+8))-1) + (size_t)s*(1<<e) + j;
            d = tk[node*128 + k] - tk[node*128 + 64 + k];
        }
        __nv_bfloat16 h, lo; split2(d, h, lo);
        g_kdh[(size_t)gr*72 + k] = h; g_kdl[(size_t)gr*72 + k] = lo;
    } else if (bid < 32768){                // ---- V ----
        int gr = (bid - 16384)*4 + lr;
        int s = gr >> 8, r = gr & 255;
        size_t leaf = (size_t)s*256 + (__brev((unsigned)r) >> 24);
        float v = tv[leaf*64 + k];
        __nv_bfloat16 h, lo; split2(v, h, lo);
        g_vh[(size_t)gr*72 + k] = h; g_vl[(size_t)gr*72 + k] = lo;
    } else if (bid < 33280){                // ---- Q ----
        int b = (bid - 32768)*4 + lr;
        __nv_bfloat16 h, lo; split2(q[(size_t)b*64 + k], h, lo);
        g_qh[(size_t)b*72 + k] = h; g_ql[(size_t)b*72 + k] = lo;
    } else {                                // ---- PLOG ----
        extern __shared__ float ps[];
        float* qs = ps;                     // [k][b] stride 65
        float* ks = ps + 64*65;             // [j][k] 16 nodes
        int pb = bid - 33280;
        int btile = pb >> 4, slice = pb & 15;
        int b_base = btile * 64, n0 = slice * 16;
        for (int i = tid; i < 64*64; i += 256){
            int b = i >> 6, kk = i & 63;
            qs[kk*65 + b] = q[(size_t)(b_base + b)*64 + kk];
        }
        for (int i = tid; i < 16*64; i += 256){
            int j = i >> 6, kk = i & 63;
            int n = n0 + j;
            ks[i] = (n < 255) ? (tk[(size_t)n*128 + kk] - tk[(size_t)n*128 + 64 + kk]) : 0.f;
        }
        __syncthreads();
        int b = tid & 63, sub = tid >> 6;
        #pragma unroll
        for (int j2 = 0; j2 < 4; j2++){
            int j = sub*4 + j2, n = n0 + j;
            if (n >= 255) break;
            float acc = 0.f;
            #pragma unroll 16
            for (int kk = 0; kk < 64; kk++)
                acc = fmaf(qs[kk*65 + b], ks[j*64 + kk], acc);
            g_plog[(size_t)n*2048 + b_base + b] = acc;
        }
    }
}

// ----------------------------- main kernel -----------------------------
// T: slot-major float[257][72]. slot 0 = base prob; slot 2^e+pos = sigma of
// expansion level e; cum(pos) at slot pos. Levels 6+7 fused: each item reads
// 8 slots and writes packed split-bf16 leaf pairs back into exactly those
// slots (self-freed, hazard-free), hi via slotH permutation, lo at +128.
__global__ __launch_bounds__(256, 2)
void tree_kernel(float* __restrict__ out)
{
    extern __shared__ char smc[];
    float* fT = (float*)smc;
    uint32_t* uT = (uint32_t*)smc;
    float* fPB = (float*)(smc + SB_PB);
    const uint32_t SB = cvta(smc);
    const int tid = threadIdx.x, w = tid >> 5, l = tid & 31;
    const int btile = blockIdx.x, sg = blockIdx.y;
    const int b_base = btile * 64;
    const int bt = w & 3, grp = w >> 2;
    const int total = NS * 8;

    auto issue = [&](int t){
        if (t >= total) return;
        int c = t & 7, si = t >> 3;
        size_t off = ((size_t)(sg*NS + si)*256 + (size_t)(c & 3)*64)*72;
        const __nv_bfloat16 *ph = (c < 4) ? g_kdh + off : g_vh + off;
        const __nv_bfloat16 *pl = (c < 4) ? g_kdl + off : g_vl + off;
        uint32_t dst = SB + SB_BUF + (uint32_t)(t & 1)*18432;
        for (int i = tid; i < 576; i += 256){
            cp16(dst + i*16,        (const char*)ph + i*16);
            cp16(dst + 9216 + i*16, (const char*)pl + i*16);
        }
        CP_COMMIT();
    };

    issue(0); issue(1);

    // ---- Q fragments -> registers ----
    uint32_t QAh[4][4], QAl[4][4];
    {
        int r0 = b_base + bt*16 + (l >> 2);
        int c0 = 2 * (l & 3);
        #pragma unroll
        for (int kt = 0; kt < 4; kt++){
            int k0 = kt*16 + c0;
            QAh[kt][0] = *(const uint32_t*)&g_qh[(size_t)r0*72 + k0];
            QAh[kt][1] = *(const uint32_t*)&g_qh[(size_t)(r0+8)*72 + k0];
            QAh[kt][2] = *(const uint32_t*)&g_qh[(size_t)r0*72 + k0 + 8];
            QAh[kt][3] = *(const uint32_t*)&g_qh[(size_t)(r0+8)*72 + k0 + 8];
            QAl[kt][0] = *(const uint32_t*)&g_ql[(size_t)r0*72 + k0];
            QAl[kt][1] = *(const uint32_t*)&g_ql[(size_t)(r0+8)*72 + k0];
            QAl[kt][2] = *(const uint32_t*)&g_ql[(size_t)r0*72 + k0 + 8];
            QAl[kt][3] = *(const uint32_t*)&g_ql[(size_t)(r0+8)*72 + k0 + 8];
        }
    }

    // ---- 9 path logits per batch -> base probs ----
    for (int i = tid; i < 9*64; i += 256){
        int n = i >> 6, b = i & 63;
        int node = (n < 7) ? ((1 << n) - 1 + (sg >> (6 - n)))
                           : (127 + 2*sg + (n - 7));
        fT[n*64 + b] = g_plog[(size_t)node*2048 + b_base + b];
    }
    __syncthreads();
    if (tid < 64){
        int b = tid;
        float common = 1.f;
        #pragma unroll
        for (int e = 0; e < 6; e++){
            int bit = (sg >> (5 - e)) & 1;
            float x = fT[e*64 + b];
            common *= fast_sigmoid(bit ? -x : x);
        }
        float s6  = fast_sigmoid(fT[6*64 + b]);
        float s7a = fast_sigmoid(fT[7*64 + b]);
        float s7b = fast_sigmoid(fT[8*64 + b]);
        fPB[0*64 + b] = common * s6 * s7a;
        fPB[1*64 + b] = common * s6 * (1.f - s7a);
        fPB[2*64 + b] = common * (1.f - s6) * s7b;
        fPB[3*64 + b] = common * (1.f - s6) * (1.f - s7b);
    }

    float acc2[4][4];
    #pragma unroll
    for (int i = 0; i < 4; i++)
        #pragma unroll
        for (int j = 0; j < 4; j++) acc2[i][j] = 0.f;

    for (int si = 0; si < NS; si++){
        // ---------------- GEMM1: 4 passes of 64 n-columns ----------------
        for (int p = 0; p < 4; p++){
            int t = si*8 + p;
            if (t + 1 < total) CP_WAIT(1); else CP_WAIT(0);
            __syncthreads();
            uint32_t kb = SB + SB_BUF + (uint32_t)(t & 1)*18432;
            float a1[4][4];
            #pragma unroll
            for (int i = 0; i < 4; i++)
                #pragma unroll
                for (int j = 0; j < 4; j++) a1[i][j] = 0.f;
            #pragma unroll
            for (int kt = 0; kt < 4; kt++){
                #pragma unroll
                for (int ntp = 0; ntp < 2; ntp++){
                    uint32_t bo = kb + (uint32_t)((
                        (grp*32 + ntp*16 + (((l >> 4) & 1) << 3) + (l & 7))*72
                        + kt*16 + (((l >> 3) & 1) << 3)) << 1);
                    uint32_t Bh[4], Bl[4];
                    ldsm4(Bh, bo); ldsm4(Bl, bo + 9216);
                    mma(a1[2*ntp],   QAh[kt], Bh[0], Bh[1]);
                    mma(a1[2*ntp],   QAh[kt], Bl[0], Bl[1]);
                    mma(a1[2*ntp],   QAl[kt], Bh[0], Bh[1]);
                    mma(a1[2*ntp+1], QAh[kt], Bh[2], Bh[3]);
                    mma(a1[2*ntp+1], QAh[kt], Bl[2], Bl[3]);
                    mma(a1[2*ntp+1], QAl[kt], Bh[2], Bh[3]);
                }
            }
            // sigma fused: store sigma(logit) into slot-major T [1+node][b]
            #pragma unroll
            for (int nt = 0; nt < 4; nt++){
                int r = bt*16 + (l >> 2);
                int cc = p*64 + grp*32 + nt*8 + 2*(l & 3);
                fT[(1 + cc)*72 + r]       = fast_sigmoid(a1[nt][0]);
                fT[(2 + cc)*72 + r]       = fast_sigmoid(a1[nt][1]);
                fT[(1 + cc)*72 + r + 8]   = fast_sigmoid(a1[nt][2]);
                fT[(2 + cc)*72 + r + 8]   = fast_sigmoid(a1[nt][3]);
            }
            __syncthreads();
            if (t + 2 < total) issue(t + 2);
        }
        if (tid < 64) fT[tid] = fPB[si*64 + tid];   // slot 0
        __syncthreads();

        // ------- expansion: fused triple levels, in-place -------
        {
            const int wb = w * 8;
            // step A: levels 0,1,2 (1 parent -> 8); lanes 0-3
            if (l < 4){
                int b2 = wb + 2*l;
                float2 v   = *(float2*)&fT[0*72 + b2];
                float2 s0  = *(float2*)&fT[1*72 + b2];
                float2 s10 = *(float2*)&fT[2*72 + b2];
                float2 s11 = *(float2*)&fT[3*72 + b2];
                float2 s2[4];
                #pragma unroll
                for (int j = 0; j < 4; j++) s2[j] = *(float2*)&fT[(4+j)*72 + b2];
                float2 a0{v.x*s0.x, v.y*s0.y}, a1v{v.x-a0.x, v.y-a0.y};
                float2 bb[4];
                bb[0] = {a0.x*s10.x,  a0.y*s10.y};  bb[2] = {a0.x-bb[0].x,  a0.y-bb[0].y};
                bb[1] = {a1v.x*s11.x, a1v.y*s11.y}; bb[3] = {a1v.x-bb[1].x, a1v.y-bb[1].y};
                #pragma unroll
                for (int j = 0; j < 4; j++){
                    float2 c0{bb[j].x*s2[j].x, bb[j].y*s2[j].y};
                    float2 c1{bb[j].x-c0.x,    bb[j].y-c0.y};
                    *(float2*)&fT[j*72 + b2]     = c0;
                    *(float2*)&fT[(j+4)*72 + b2] = c1;
                }
            }
            __syncwarp();
            // step B: levels 3,4,5 (8 parents -> 64); 32 lanes
            {
                int pos = l >> 2, b2 = wb + 2*(l & 3);
                float2 v   = *(float2*)&fT[pos*72 + b2];
                float2 s3  = *(float2*)&fT[(8+pos)*72 + b2];
                float2 s40 = *(float2*)&fT[(16+pos)*72 + b2];
                float2 s41 = *(float2*)&fT[(24+pos)*72 + b2];
                float2 s5[4];
                #pragma unroll
                for (int j = 0; j < 4; j++) s5[j] = *(float2*)&fT[(32+8*j+pos)*72 + b2];
                float2 a0{v.x*s3.x, v.y*s3.y}, a1v{v.x-a0.x, v.y-a0.y};
                float2 bb[4];
                bb[0] = {a0.x*s40.x,  a0.y*s40.y};  bb[2] = {a0.x-bb[0].x,  a0.y-bb[0].y};
                bb[1] = {a1v.x*s41.x, a1v.y*s41.y}; bb[3] = {a1v.x-bb[1].x, a1v.y-bb[1].y};
                #pragma unroll
                for (int j = 0; j < 4; j++){
                    float2 c0{bb[j].x*s5[j].x, bb[j].y*s5[j].y};
                    float2 c1{bb[j].x-c0.x,    bb[j].y-c0.y};
                    *(float2*)&fT[(8*j+pos)*72 + b2]    = c0;
                    *(float2*)&fT[(32+8*j+pos)*72 + b2] = c1;
                }
            }
            __syncwarp();
            // fused levels 6+7 + split-pack: item (pp, batch-pair) reads 8
            // slots {2pp,2pp+1, 64+2pp,65+2pp, 128+2pp,129+2pp, 192+2pp,193+2pp}
            // and writes leaf pairs P=pp,pp+32,pp+64,pp+96 into exactly those
            // slots (hi via slotH, lo at slotH+128). Self-freed.
            #pragma unroll
            for (int ii = 0; ii < 4; ii++){
                int it = l + ii*32;
                int pp = it >> 2, b2 = wb + 2*(it & 3);   // pp 0..31
                int s0 = 2*pp;
                float2 v0 = *(float2*)&fT[s0*72 + b2];          // cum parent 2pp
                float2 v1 = *(float2*)&fT[(s0+1)*72 + b2];      // cum parent 2pp+1
                float2 g0 = *(float2*)&fT[(64+s0)*72 + b2];     // sigma6(2pp)
                float2 g1 = *(float2*)&fT[(65+s0)*72 + b2];     // sigma6(2pp+1)
                float2 t0 = *(float2*)&fT[(128+s0)*72 + b2];    // sigma7(2pp)
                float2 t1 = *(float2*)&fT[(129+s0)*72 + b2];    // sigma7(2pp+1)
                float2 t2 = *(float2*)&fT[(192+s0)*72 + b2];    // sigma7(2pp+64)
                float2 t3 = *(float2*)&fT[(193+s0)*72 + b2];    // sigma7(2pp+65)
                // level 6
                float2 cA0{v0.x*g0.x, v0.y*g0.y}, cA1{v0.x-cA0.x, v0.y-cA0.y};
                float2 cB0{v1.x*g1.x, v1.y*g1.y}, cB1{v1.x-cB0.x, v1.y-cB0.y};
                // level 7 leaves
                float2 L0a{cA0.x*t0.x, cA0.y*t0.y};             // leaf 2pp
                float2 L0b{cB0.x*t1.x, cB0.y*t1.y};             // leaf 2pp+1
                float2 L2a{cA0.x-L0a.x, cA0.y-L0a.y};           // leaf 2pp+128
                float2 L2b{cB0.x-L0b.x, cB0.y-L0b.y};           // leaf 2pp+129
                float2 L1a{cA1.x*t2.x, cA1.y*t2.y};             // leaf 2pp+64
                float2 L1b{cB1.x*t3.x, cB1.y*t3.y};             // leaf 2pp+65
                float2 L3a{cA1.x-L1a.x, cA1.y-L1a.y};           // leaf 2pp+192
                float2 L3b{cB1.x-L1b.x, cB1.y-L1b.y};           // leaf 2pp+193
                uint2 H, L;
                int sh;
                sh = slotH(pp);                                  // pair (2pp,2pp+1)
                splitpair(L0a.x, L0b.x, H.x, L.x);
                splitpair(L0a.y, L0b.y, H.y, L.y);
                *(uint2*)&uT[sh*72 + b2] = H; *(uint2*)&uT[(sh+128)*72 + b2] = L;
                sh = slotH(pp + 32);                             // pair (2pp+64,2pp+65)
                splitpair(L1a.x, L1b.x, H.x, L.x);
                splitpair(L1a.y, L1b.y, H.y, L.y);
                *(uint2*)&uT[sh*72 + b2] = H; *(uint2*)&uT[(sh+128)*72 + b2] = L;
                sh = slotH(pp + 64);                             // pair (2pp+128,2pp+129)
                splitpair(L2a.x, L2b.x, H.x, L.x);
                splitpair(L2a.y, L2b.y, H.y, L.y);
                *(uint2*)&uT[sh*72 + b2] = H; *(uint2*)&uT[(sh+128)*72 + b2] = L;
                sh = slotH(pp + 96);                             // pair (2pp+192,2pp+193)
                splitpair(L3a.x, L3b.x, H.x, L.x);
                splitpair(L3a.y, L3b.y, H.y, L.y);
                *(uint2*)&uT[sh*72 + b2] = H; *(uint2*)&uT[(sh+128)*72 + b2] = L;
            }
        }
        __syncthreads();

        // ---------------- GEMM2: 4 k-chunks, register accumulator ----------------
        for (int c = 0; c < 4; c++){
            int t = si*8 + 4 + c;
            if (t + 1 < total) CP_WAIT(1); else CP_WAIT(0);
            __syncthreads();
            uint32_t vb = SB + SB_BUF + (uint32_t)(t & 1)*18432;
            #pragma unroll
            for (int kt = 0; kt < 4; kt++){
                int r0 = bt*16 + (l >> 2);
                int Pb = c*32 + kt*8;
                int Pa = Pb + (l & 3), Pc = Pb + 4 + (l & 3);
                int sa = slotH(Pa), sc = slotH(Pc);
                uint32_t Ah[4], Al[4];
                Ah[0] = uT[sa*72 + r0];
                Ah[1] = uT[sa*72 + r0 + 8];
                Ah[2] = uT[sc*72 + r0];
                Ah[3] = uT[sc*72 + r0 + 8];
                Al[0] = uT[(sa+128)*72 + r0];
                Al[1] = uT[(sa+128)*72 + r0 + 8];
                Al[2] = uT[(sc+128)*72 + r0];
                Al[3] = uT[(sc+128)*72 + r0 + 8];
                #pragma unroll
                for (int dtp = 0; dtp < 2; dtp++){
                    uint32_t bo = vb + (uint32_t)((
                        (kt*16 + (((l >> 3) & 1) << 3) + (l & 7))*72
                        + grp*32 + dtp*16 + (((l >> 4) & 1) << 3)) << 1);
                    uint32_t Bh[4], Bl[4];
                    ldsm4t(Bh, bo); ldsm4t(Bl, bo + 9216);
                    mma(acc2[2*dtp],   Ah, Bh[0], Bh[1]);
                    mma(acc2[2*dtp],   Ah, Bl[0], Bl[1]);
                    mma(acc2[2*dtp],   Al, Bh[0], Bh[1]);
                    mma(acc2[2*dtp+1], Ah, Bh[2], Bh[3]);
                    mma(acc2[2*dtp+1], Ah, Bl[2], Bl[3]);
                    mma(acc2[2*dtp+1], Al, Bh[2], Bh[3]);
                }
            }
            __syncthreads();
            if (t + 2 < total) issue(t + 2);
        }
    }

    // ---------------- epilogue: one atomic pass per CTA ----------------
    #pragma unroll
    for (int dt = 0; dt < 4; dt++){
        int r = b_base + bt*16 + (l >> 2);
        int cc = grp*32 + dt*8 + 2*(l & 3);
        atomicAdd(&out[(size_t)r*64 + cc],         acc2[dt][0]);
        atomicAdd(&out[(size_t)r*64 + cc + 1],     acc2[dt][1]);
        atomicAdd(&out[(size_t)(r+8)*64 + cc],     acc2[dt][2]);
        atomicAdd(&out[(size_t)(r+8)*64 + cc + 1], acc2[dt][3]);
    }
}

extern "C" void kernel_launch(void* const* d_in, const int* in_sizes, int n_in,
                              void* d_out, int out_size) {
    const float* q  = (const float*)d_in[0];
    const float* tk = (const float*)d_in[1];
    const float* tv = (const float*)d_in[2];
    float* out = (float*)d_out;

    cudaFuncSetAttribute(tree_kernel,
                         cudaFuncAttributeMaxDynamicSharedMemorySize, SMEM_BYTES);

    cudaMemsetAsync(out, 0, (size_t)2048 * 64 * sizeof(float));
    prep_all<<<33792, 256, PLOG_SMEM>>>(q, tk, tv);
    tree_kernel<<<dim3(32, 64), 256, SMEM_BYTES>>>(out);
}